// round 3
// baseline (speedup 1.0000x reference)
#include <cuda_runtime.h>
#include <cstdint>

// Problem constants
#define SIN   512          // input H=W
#define HW    128          // resized H=W and volume H=W
#define ND    128          // depth bins
#define NB    8            // batch

// Scratch: per-pixel {xray_resized, (float)d_idx}
__device__ float2 g_pix[NB * HW * HW];

// ---------------------------------------------------------------------------
// Kernel A: jax.image.resize(bilinear, antialias) 512->128, fused d_idx.
// R3: each block produces TWO adjacent output rows, loading the 12-row input
// union once (adjacent 8-tap windows overlap by 4 rows). W-weights shared.
// Arithmetic identical to the R1 version that passed at 8e-8.
// ---------------------------------------------------------------------------
__global__ __launch_bounds__(128) void resize_kernel(
    const float* __restrict__ depth, const float* __restrict__ xray)
{
    __shared__ float2 hrow[2][SIN];   // H-contracted rows: {d, x}

    const int hp  = blockIdx.x;       // 0..63: output row pair
    const int b   = blockIdx.y;       // 0..7
    const int tid = threadIdx.x;      // 128 threads

    const float BW[8] = {0.125f, 0.375f, 0.625f, 0.875f,
                         0.875f, 0.625f, 0.375f, 0.125f};

    const int ho0 = hp * 2;
    const int ho1 = ho0 + 1;
    const int r0  = 8 * hp - 2;       // first input row of the 12-row union

    // Per-output-row normalized H weights (exactly as R1)
    float whn0[8], whn1[8];
    {
        float hs0 = 0.f, hs1 = 0.f;
        const int ih0a = 4 * ho0 - 2;
        const int ih0b = 4 * ho1 - 2;
        #pragma unroll
        for (int k = 0; k < 8; k++) {
            int ia = ih0a + k, ib = ih0b + k;
            float wa = (ia >= 0 && ia < SIN) ? BW[k] : 0.f;
            float wb = (ib >= 0 && ib < SIN) ? BW[k] : 0.f;
            whn0[k] = wa; hs0 += wa;
            whn1[k] = wb; hs1 += wb;
        }
        #pragma unroll
        for (int k = 0; k < 8; k++) {
            whn0[k] = __fdiv_rn(whn0[k], hs0);
            whn1[k] = __fdiv_rn(whn1[k], hs1);
        }
    }
    // Map to the 12-row union: row j (global r0+j) has weight
    //   w0[j] = whn0[j]      for j in [0,8)
    //   w1[j] = whn1[j-4]    for j in [4,12)
    float w0[12], w1[12];
    #pragma unroll
    for (int j = 0; j < 12; j++) {
        w0[j] = (j < 8) ? whn0[j] : 0.f;
        w1[j] = (j >= 4) ? whn1[j - 4] : 0.f;
    }

    const float* dbase = depth + (size_t)b * SIN * SIN;
    const float* xbase = xray  + (size_t)b * SIN * SIN;

    // Stage 1: H contraction for both output rows, one pass over 12 rows.
    {
        const int c0 = tid * 4;
        float4 ad0 = make_float4(0.f,0.f,0.f,0.f), ax0 = ad0;
        float4 ad1 = ad0, ax1 = ad0;
        #pragma unroll
        for (int j = 0; j < 12; j++) {
            const int r = r0 + j;
            if (r < 0 || r >= SIN) continue;     // both weights are zero there
            const float4 dv = *(const float4*)(dbase + (size_t)r * SIN + c0);
            const float4 xv = *(const float4*)(xbase + (size_t)r * SIN + c0);
            const float a = w0[j], c = w1[j];
            ad0.x = fmaf(a, dv.x, ad0.x); ad0.y = fmaf(a, dv.y, ad0.y);
            ad0.z = fmaf(a, dv.z, ad0.z); ad0.w = fmaf(a, dv.w, ad0.w);
            ax0.x = fmaf(a, xv.x, ax0.x); ax0.y = fmaf(a, xv.y, ax0.y);
            ax0.z = fmaf(a, xv.z, ax0.z); ax0.w = fmaf(a, xv.w, ax0.w);
            ad1.x = fmaf(c, dv.x, ad1.x); ad1.y = fmaf(c, dv.y, ad1.y);
            ad1.z = fmaf(c, dv.z, ad1.z); ad1.w = fmaf(c, dv.w, ad1.w);
            ax1.x = fmaf(c, xv.x, ax1.x); ax1.y = fmaf(c, xv.y, ax1.y);
            ax1.z = fmaf(c, xv.z, ax1.z); ax1.w = fmaf(c, xv.w, ax1.w);
        }
        hrow[0][c0+0] = make_float2(ad0.x, ax0.x);
        hrow[0][c0+1] = make_float2(ad0.y, ax0.y);
        hrow[0][c0+2] = make_float2(ad0.z, ax0.z);
        hrow[0][c0+3] = make_float2(ad0.w, ax0.w);
        hrow[1][c0+0] = make_float2(ad1.x, ax1.x);
        hrow[1][c0+1] = make_float2(ad1.y, ax1.y);
        hrow[1][c0+2] = make_float2(ad1.z, ax1.z);
        hrow[1][c0+3] = make_float2(ad1.w, ax1.w);
    }
    __syncthreads();

    // Stage 2: W contraction. Same wwn for both rows (depends only on wo).
    const int wo  = tid;
    const int iw0 = 4 * wo - 2;

    float wwn[8]; float ws = 0.f;
    #pragma unroll
    for (int k = 0; k < 8; k++) {
        int iw = iw0 + k;
        float w = (iw >= 0 && iw < SIN) ? BW[k] : 0.f;
        wwn[k] = w; ws += w;
    }
    #pragma unroll
    for (int k = 0; k < 8; k++) wwn[k] = __fdiv_rn(wwn[k], ws);

    #pragma unroll
    for (int half = 0; half < 2; half++) {
        float ad = 0.f, ax = 0.f;
        #pragma unroll
        for (int k = 0; k < 8; k++) {
            if (wwn[k] != 0.f) {
                float2 q = hrow[half][iw0 + k];
                ad = fmaf(wwn[k], q.x, ad);
                ax = fmaf(wwn[k], q.y, ax);
            }
        }
        // d_idx = clip(int32((d/100)*127), 0, 127) — IEEE ops to match reference
        float nd = __fdiv_rn(ad, 100.0f);
        int di = (int)__fmul_rn(nd, 127.0f);
        di = min(max(di, 0), ND - 1);
        g_pix[((size_t)b * HW + (ho0 + half)) * HW + wo] = make_float2(ax, (float)di);
    }
}

// ---------------------------------------------------------------------------
// Kernel B: fused depth-splat + 3x3x3 box average.
//   out[b,d,h,w] = sum over 3x3 (h,w) nbhd of prof[n][d - pd0[n]]
// prof = (x/27) * box3-of-clipped-gauss5, 7-tap profile per pixel.
//
// R3: 512 threads/block, 4-way depth-PHASE split — four threads per column,
// thread phase p handles only taps with (d&3)==p. Same wavefront total, but
// 48 warps/SM (~75% occ) to saturate the L1TEX pipe.
// ---------------------------------------------------------------------------
__global__ __launch_bounds__(512) void splat_pool_kernel(float* __restrict__ out)
{
    extern __shared__ float sm[];
    float* acc  = sm;                         // [128][128] = 16384 floats
    float* prof = sm + 16384;                 // [180][7]  (weights include /27)
    int*   pd0  = (int*)(sm + 16384 + 1260);  // [180]
    float* sP   = sm + 16384 + 1260 + 180;    // [6] prefix sums of gauss5/27

    const int tid = threadIdx.x;              // 0..511
    const int p   = tid >> 7;                 // depth phase (mod 4) this thread owns
    const int ct  = tid & 127;                // column within 8x16 tile
    const int w0  = blockIdx.x * 16;
    const int h0  = blockIdx.y * 8;
    const int b   = blockIdx.z;

    const float inv27 = 1.0f / 27.0f;
    const float E1 = 0.60653065971263342f * inv27;  // exp(-0.5)/27
    const float E2 = 0.13533528323661270f * inv27;  // exp(-2)/27
    const float E0 = inv27;

    if (tid == 0) {
        sP[0] = 0.f;
        sP[1] = E2;
        sP[2] = E2 + E1;
        sP[3] = E2 + E1 + E0;
        sP[4] = E2 + E1 + E0 + E1;
        sP[5] = E2 + E1 + E0 + E1 + E2;
    }

    // Zero the accumulator tile (float4 STS, 8 per thread)
    {
        float4* a4 = (float4*)acc;
        #pragma unroll
        for (int i = tid; i < 4096; i += 512)
            a4[i] = make_float4(0.f, 0.f, 0.f, 0.f);
    }
    __syncthreads();

    // Per-pixel 7-tap profiles for the 10x18 halo tile (one pixel per thread).
    if (tid < 180) {
        const int n  = tid;
        const int ph = h0 + n / 18 - 1;
        const int pw = w0 + n % 18 - 1;
        float x = 0.f; int di = 3;
        if (ph >= 0 && ph < HW && pw >= 0 && pw < HW) {
            float2 q = g_pix[((size_t)b * HW + ph) * HW + pw];
            x = q.x; di = (int)q.y;
        }
        const int lo = max(-2, -di);
        const int hi = min(2, (ND - 1) - di);
        pd0[n] = di - 3;
        #pragma unroll
        for (int k = 0; k < 7; k++) {
            int jl = max(k - 4, lo);
            int jh = min(k - 2, hi);
            float w = (jh >= jl) ? (sP[jh + 3] - sP[jl + 2]) : 0.f;
            prof[n * 7 + k] = x * w;
        }
    }
    __syncthreads();

    // Accumulate the 9-neighbor sum into this thread's (column, phase) taps.
    {
        const int ty = ct >> 4;       // 0..7  (h within tile)
        const int tx = ct & 15;       // 0..15 (w within tile)
        #pragma unroll
        for (int dh = 0; dh < 3; dh++) {
            #pragma unroll
            for (int dw = 0; dw < 3; dw++) {
                const int n  = (ty + dh) * 18 + (tx + dw);
                const int d0 = pd0[n];
                const int ks = (p - d0) & 3;     // first tap of my phase
                #pragma unroll
                for (int kk = 0; kk < 2; kk++) {
                    const int k = ks + 4 * kk;
                    const int d = d0 + k;
                    if (k < 7 && d >= 0 && d < ND)
                        acc[d * 128 + ct] += prof[n * 7 + k];
                }
            }
        }
    }
    __syncthreads();

    // Coalesced float4 writeout (/27 already folded into prof).
    {
        #pragma unroll
        for (int it = 0; it < 8; it++) {
            const int i    = tid + 512 * it;     // float4 index in acc
            const int d    = i >> 5;             // 32 float4 per d-slice
            const int col4 = (i & 31) * 4;       // column of first float
            const int oy   = col4 >> 4;          // 0..7
            const int ox   = col4 & 15;          // 0,4,8,12
            float4 v = *(float4*)&acc[d * 128 + col4];
            *(float4*)&out[(((size_t)b * ND + d) * HW + (h0 + oy)) * HW + w0 + ox] = v;
        }
    }
}

// ---------------------------------------------------------------------------
extern "C" void kernel_launch(void* const* d_in, const int* in_sizes, int n_in,
                              void* d_out, int out_size)
{
    const float* depth = (const float*)d_in[0];
    const float* xray  = (const float*)d_in[1];
    float* out = (float*)d_out;

    // Kernel A: resize + d_idx (2 output rows per block)
    resize_kernel<<<dim3(HW / 2, NB), 128>>>(depth, xray);

    // Kernel B: splat + 3x3x3 box average
    const int smem_b = (16384 + 180 * 7) * (int)sizeof(float)
                     + 180 * (int)sizeof(int)
                     + 6 * (int)sizeof(float);
    cudaFuncSetAttribute(splat_pool_kernel,
                         cudaFuncAttributeMaxDynamicSharedMemorySize, smem_b);
    splat_pool_kernel<<<dim3(HW / 16, HW / 8, NB), 512, smem_b>>>(out);
}

// round 4
// speedup vs baseline: 1.1715x; 1.1715x over previous
#include <cuda_runtime.h>
#include <cstdint>

// Problem constants
#define SIN   512          // input H=W
#define HW    128          // resized H=W and volume H=W
#define ND    128          // depth bins
#define NB    8            // batch

// Scratch: per-pixel {xray_resized, (float)d_idx}
__device__ float2 g_pix[NB * HW * HW];

// ---------------------------------------------------------------------------
// Kernel A: jax.image.resize(bilinear, antialias) 512->128 for both arrays,
// fused with d_idx computation.  (R1 version, verbatim — measured ~5.5us)
// ---------------------------------------------------------------------------
__global__ __launch_bounds__(128) void resize_kernel(
    const float* __restrict__ depth, const float* __restrict__ xray)
{
    __shared__ float2 hrow[SIN];   // H-contracted row at this output row: {d, x}

    const int ho  = blockIdx.x;    // 0..127
    const int b   = blockIdx.y;    // 0..7
    const int tid = threadIdx.x;   // 128 threads

    const float BW[8] = {0.125f, 0.375f, 0.625f, 0.875f,
                         0.875f, 0.625f, 0.375f, 0.125f};

    const int ih0 = 4 * ho - 2;

    float whn[8]; float hs = 0.f;
    #pragma unroll
    for (int k = 0; k < 8; k++) {
        int ih = ih0 + k;
        float w = (ih >= 0 && ih < SIN) ? BW[k] : 0.f;
        whn[k] = w; hs += w;
    }
    #pragma unroll
    for (int k = 0; k < 8; k++) whn[k] = __fdiv_rn(whn[k], hs);

    const float* dbase = depth + (size_t)b * SIN * SIN;
    const float* xbase = xray  + (size_t)b * SIN * SIN;

    {
        const int c0 = tid * 4;
        float4 ad = make_float4(0.f, 0.f, 0.f, 0.f);
        float4 ax = make_float4(0.f, 0.f, 0.f, 0.f);
        #pragma unroll
        for (int kh = 0; kh < 8; kh++) {
            if (whn[kh] != 0.f) {
                const int ih = ih0 + kh;
                const float4 dv = *(const float4*)(dbase + (size_t)ih * SIN + c0);
                const float4 xv = *(const float4*)(xbase + (size_t)ih * SIN + c0);
                const float w = whn[kh];
                ad.x = fmaf(w, dv.x, ad.x); ad.y = fmaf(w, dv.y, ad.y);
                ad.z = fmaf(w, dv.z, ad.z); ad.w = fmaf(w, dv.w, ad.w);
                ax.x = fmaf(w, xv.x, ax.x); ax.y = fmaf(w, xv.y, ax.y);
                ax.z = fmaf(w, xv.z, ax.z); ax.w = fmaf(w, xv.w, ax.w);
            }
        }
        hrow[c0 + 0] = make_float2(ad.x, ax.x);
        hrow[c0 + 1] = make_float2(ad.y, ax.y);
        hrow[c0 + 2] = make_float2(ad.z, ax.z);
        hrow[c0 + 3] = make_float2(ad.w, ax.w);
    }
    __syncthreads();

    const int wo  = tid;
    const int iw0 = 4 * wo - 2;

    float wwn[8]; float ws = 0.f;
    #pragma unroll
    for (int k = 0; k < 8; k++) {
        int iw = iw0 + k;
        float w = (iw >= 0 && iw < SIN) ? BW[k] : 0.f;
        wwn[k] = w; ws += w;
    }
    #pragma unroll
    for (int k = 0; k < 8; k++) wwn[k] = __fdiv_rn(wwn[k], ws);

    float ad = 0.f, ax = 0.f;
    #pragma unroll
    for (int k = 0; k < 8; k++) {
        if (wwn[k] != 0.f) {
            float2 p = hrow[iw0 + k];
            ad = fmaf(wwn[k], p.x, ad);
            ax = fmaf(wwn[k], p.y, ax);
        }
    }

    // d_idx = clip(int32((d/100)*127), 0, 127) — IEEE ops to match reference
    float nd = __fdiv_rn(ad, 100.0f);
    int di = (int)__fmul_rn(nd, 127.0f);
    di = min(max(di, 0), ND - 1);

    g_pix[((size_t)b * HW + ho) * HW + wo] = make_float2(ax, (float)di);
}

// ---------------------------------------------------------------------------
// Kernel B (R4): raw 5-tap gaussian splat into acc[d][col], depth-box folded
// into the WRITEOUT as a 3-tap running sum over d. No profile arrays:
// tap weights are compile-time constants (with /27 folded in).
//
//   g[d][c]  = sum over 3x3 nbhd pixels n of x_n * W[d - (di_n - 2)]  (taps
//              outside [0,127] dropped = reference valid mask)
//   out[d][c] = g[d-1][c] + g[d][c] + g[d+1][c]   (zero-padded ends)
//
// 256 threads: RMW phase uses 2 threads/column (depth parity split, no races);
// writeout uses 4-column float4 groups walking d with lagged registers.
// ---------------------------------------------------------------------------
__global__ __launch_bounds__(256) void splat_pool_kernel(float* __restrict__ out)
{
    extern __shared__ float sm[];
    float*  acc = sm;                   // [128][128] = 64KB
    float2* pix = (float2*)(sm + 16384);// [180] halo {x, d_idx}

    const int tid = threadIdx.x;        // 0..255
    const int w0  = blockIdx.x * 16;
    const int h0  = blockIdx.y * 8;
    const int b   = blockIdx.z;

    const float inv27 = 1.0f / 27.0f;
    const float W0 = 0.13533528323661270f * inv27;  // exp(-2)/27
    const float W1 = 0.60653065971263342f * inv27;  // exp(-0.5)/27
    const float W2 = inv27;                         // exp(0)/27
    // taps k=0..4 at d = (di-2)+k with weights W[k] = {W0,W1,W2,W1,W0}

    // Zero the accumulator tile (float4 STS, 16 per thread)
    {
        float4* a4 = (float4*)acc;
        #pragma unroll
        for (int i = tid; i < 4096; i += 256)
            a4[i] = make_float4(0.f, 0.f, 0.f, 0.f);
    }
    // Stage the 10x18 halo pixel map
    if (tid < 180) {
        const int ph = h0 + tid / 18 - 1;
        const int pw = w0 + tid % 18 - 1;
        float2 q = make_float2(0.f, 64.f);
        if (ph >= 0 && ph < HW && pw >= 0 && pw < HW)
            q = g_pix[((size_t)b * HW + ph) * HW + pw];
        pix[tid] = q;
    }
    __syncthreads();

    // Splat: 9 neighbors x 5 gaussian taps, parity-split over d (no races).
    {
        const int p  = tid >> 7;        // depth parity this thread owns
        const int ct = tid & 127;       // column within 8x16 tile
        const int ty = ct >> 4;         // 0..7
        const int tx = ct & 15;         // 0..15
        const float Wt[5] = {W0, W1, W2, W1, W0};
        #pragma unroll
        for (int dh = 0; dh < 3; dh++) {
            #pragma unroll
            for (int dw = 0; dw < 3; dw++) {
                const float2 q = pix[(ty + dh) * 18 + (tx + dw)];
                const float x  = q.x;
                const int   ds = (int)q.y - 2;       // first tap depth
                const int   ks = (p ^ (ds & 1)) & 1; // first tap of my parity
                #pragma unroll
                for (int kk = 0; kk < 3; kk++) {
                    const int k = ks + 2 * kk;       // k in {0,2,4} or {1,3}
                    const int d = ds + k;
                    if (k < 5 && d >= 0 && d < ND)
                        acc[d * 128 + ct] = fmaf(x, Wt[k], acc[d * 128 + ct]);
                }
            }
        }
    }
    __syncthreads();

    // Writeout: 3-tap running sum over d, float4 across 4 columns.
    // 32 column-groups x 8 d-chunks of 16 = 256 threads.
    {
        const int g  = tid & 31;         // column group (4 cols)
        const int dc = tid >> 5;         // d-chunk 0..7
        const int d0 = dc * 16;
        const int oy = (g * 4) >> 4;     // 0..7
        const int ox = (g * 4) & 15;     // 0,4,8,12
        const float4* a4 = (const float4*)acc;   // [d][32 groups]

        float4 vm1 = (d0 == 0) ? make_float4(0.f, 0.f, 0.f, 0.f)
                               : a4[(d0 - 1) * 32 + g];
        float4 v0  = a4[d0 * 32 + g];
        const size_t obase =
            (((size_t)b * ND) * HW + (h0 + oy)) * HW + w0 + ox;
        #pragma unroll
        for (int i = 0; i < 16; i++) {
            const int d = d0 + i;
            float4 vp1 = (d == ND - 1) ? make_float4(0.f, 0.f, 0.f, 0.f)
                                       : a4[(d + 1) * 32 + g];
            float4 o;
            o.x = vm1.x + v0.x + vp1.x;
            o.y = vm1.y + v0.y + vp1.y;
            o.z = vm1.z + v0.z + vp1.z;
            o.w = vm1.w + v0.w + vp1.w;
            *(float4*)&out[obase + (size_t)d * HW * HW] = o;
            vm1 = v0; v0 = vp1;
        }
    }
}

// ---------------------------------------------------------------------------
extern "C" void kernel_launch(void* const* d_in, const int* in_sizes, int n_in,
                              void* d_out, int out_size)
{
    const float* depth = (const float*)d_in[0];
    const float* xray  = (const float*)d_in[1];
    float* out = (float*)d_out;

    // Kernel A: resize + d_idx
    resize_kernel<<<dim3(HW, NB), 128>>>(depth, xray);

    // Kernel B: splat + 3x3x3 box average
    const int smem_b = 16384 * (int)sizeof(float) + 180 * (int)sizeof(float2);
    cudaFuncSetAttribute(splat_pool_kernel,
                         cudaFuncAttributeMaxDynamicSharedMemorySize, smem_b);
    splat_pool_kernel<<<dim3(HW / 16, HW / 8, NB), 256, smem_b>>>(out);
}